// round 14
// baseline (speedup 1.0000x reference)
#include <cuda_runtime.h>
#include <cuda_bf16.h>
#include <cstdint>

#define NN 100000
#define NEDGE 1600000

// ---------------- device scratch (no allocation; referenced by name only) --
__device__ int   g_is64;
__device__ int   g_rows[NEDGE];     // packed: row | (slot_idx << 17)
__device__ int   g_cols[NEDGE];
__device__ unsigned long long g_epack[NEDGE];   // {w:f32 << 32 | col:u32}
__device__ float g_dinv[NN];
__device__ int   g_cnt[NN];
__device__ int   g_rowptr[NN];
__device__ __align__(16) float g_bufA[(size_t)NN * 128];   // GEMM out (f32)
__device__ __align__(16) float g_bufB[(size_t)NN * 128];   // SPMM out (f32)
__device__ __align__(16) __nv_bfloat16 g_W0hi[128 * 128], g_W0lo[128 * 128];
__device__ __align__(16) __nv_bfloat16 g_W1hi[128 * 128], g_W1lo[128 * 128];
__device__ __align__(16) __nv_bfloat16 g_W2hi[128 * 64],  g_W2lo[128 * 64];

__device__ __forceinline__ const __nv_bfloat16* wsel_hi(int w) {
    return w == 0 ? g_W0hi : (w == 1 ? g_W1hi : g_W2hi);
}
__device__ __forceinline__ const __nv_bfloat16* wsel_lo(int w) {
    return w == 0 ? g_W0lo : (w == 1 ? g_W1lo : g_W2lo);
}

// ---------------- helpers ----------------
__device__ __forceinline__ uint32_t s2u(const void* p) {
    return (uint32_t)__cvta_generic_to_shared(p);
}
__device__ __forceinline__ void ldsm_x4(uint32_t addr, uint32_t& r0, uint32_t& r1,
                                        uint32_t& r2, uint32_t& r3) {
    asm volatile("ldmatrix.sync.aligned.m8n8.x4.shared.b16 {%0,%1,%2,%3}, [%4];"
                 : "=r"(r0), "=r"(r1), "=r"(r2), "=r"(r3) : "r"(addr));
}
__device__ __forceinline__ void ldsm_x4t(uint32_t addr, uint32_t& r0, uint32_t& r1,
                                         uint32_t& r2, uint32_t& r3) {
    asm volatile("ldmatrix.sync.aligned.m8n8.x4.trans.shared.b16 {%0,%1,%2,%3}, [%4];"
                 : "=r"(r0), "=r"(r1), "=r"(r2), "=r"(r3) : "r"(addr));
}
__device__ __forceinline__ void mma_bf16(float* c, const uint32_t* a, const uint32_t* b) {
    asm volatile(
        "mma.sync.aligned.m16n8k16.row.col.f32.bf16.bf16.f32 "
        "{%0,%1,%2,%3},{%4,%5,%6,%7},{%8,%9},{%0,%1,%2,%3};"
        : "+f"(c[0]), "+f"(c[1]), "+f"(c[2]), "+f"(c[3])
        : "r"(a[0]), "r"(a[1]), "r"(a[2]), "r"(a[3]), "r"(b[0]), "r"(b[1]));
}
__device__ __forceinline__ void split_bf16(float v, unsigned short& hi, unsigned short& lo) {
    __nv_bfloat16 h = __float2bfloat16(v);
    float r = v - __bfloat162float(h);
    __nv_bfloat16 l = __float2bfloat16(r);
    hi = *(unsigned short*)&h;
    lo = *(unsigned short*)&l;
}
__device__ __forceinline__ void split4(float4 v, uint32_t* ph, uint32_t* pl) {
    unsigned short h[4], l[4];
    split_bf16(v.x, h[0], l[0]);
    split_bf16(v.y, h[1], l[1]);
    split_bf16(v.z, h[2], l[2]);
    split_bf16(v.w, h[3], l[3]);
    ph[0] = (uint32_t)h[0] | ((uint32_t)h[1] << 16);
    ph[1] = (uint32_t)h[2] | ((uint32_t)h[3] << 16);
    pl[0] = (uint32_t)l[0] | ((uint32_t)l[1] << 16);
    pl[1] = (uint32_t)l[2] | ((uint32_t)l[3] << 16);
}

// ---------------- k_init: zero cnt + dtype detect (block 0) ----------------
__global__ void k_init(const int* __restrict__ ei) {
    int i = blockIdx.x * blockDim.x + threadIdx.x;
    if (i < NN) g_cnt[i] = 0;
    if (blockIdx.x == 0) {
        __shared__ int bad;
        if (threadIdx.x == 0) bad = 0;
        __syncthreads();
        for (int k = threadIdx.x; k < 1024; k += blockDim.x) {
            int lo = ei[2 * k], hi = ei[2 * k + 1];
            if (hi != 0 || lo < 0 || lo >= NN) bad = 1;
        }
        __syncthreads();
        if (threadIdx.x == 0) g_is64 = (bad == 0) ? 1 : 0;
    }
}

// ---------------- k_stage1: extract+count(+slot idx) | splitW0/1/2 ---------
#define NB_EXTRACT 6250
#define NB_W0 64
#define NB_W1 64
#define NB_W2 32
#define NB_STAGE1 (NB_EXTRACT + NB_W0 + NB_W1 + NB_W2)

__device__ __forceinline__ void do_splitW(const float* __restrict__ W, int i, int n,
                                          __nv_bfloat16* hi, __nv_bfloat16* lo) {
    if (i >= n) return;
    unsigned short h, l;
    split_bf16(W[i], h, l);
    hi[i] = *(__nv_bfloat16*)&h;
    lo[i] = *(__nv_bfloat16*)&l;
}

__global__ void k_stage1(const int* __restrict__ ei,
                         const float* __restrict__ W0, const float* __restrict__ W1,
                         const float* __restrict__ W2) {
    const int b = blockIdx.x;
    const int tid = threadIdx.x;
    if (b < NB_EXTRACT) {
        int e = b * 256 + tid;
        if (e >= NEDGE) return;
        int r, c;
        if (g_is64) {
            r = ei[2 * e];
            c = ei[2 * (NEDGE + e)];
        } else {
            r = ei[e];
            c = ei[NEDGE + e];
        }
        r = min(max(r, 0), NN - 1);
        c = min(max(c, 0), NN - 1);
        int idx = atomicAdd(&g_cnt[r], 1) & 0x7FFF;   // slot within row
        g_rows[e] = r | (idx << 17);                  // NN < 2^17
        g_cols[e] = c;
    } else if (b < NB_EXTRACT + NB_W0) {
        do_splitW(W0, (b - NB_EXTRACT) * 256 + tid, 128 * 128, g_W0hi, g_W0lo);
    } else if (b < NB_EXTRACT + NB_W0 + NB_W1) {
        do_splitW(W1, (b - NB_EXTRACT - NB_W0) * 256 + tid, 128 * 128, g_W1hi, g_W1lo);
    } else {
        do_splitW(W2, (b - NB_EXTRACT - NB_W0 - NB_W1) * 256 + tid, 128 * 64, g_W2hi, g_W2lo);
    }
}

// ---------------- k_scan_dinv: single-block scan of g_cnt + dinv -----------
__global__ void k_scan_dinv() {
    __shared__ int sh[1024];
    const int tid = threadIdx.x;
    const int beg = tid * 100;
    int s = 0;
    if (beg < NN) {
#pragma unroll
        for (int j = 0; j < 25; j++) {
            int4 c = *(const int4*)&g_cnt[beg + 4 * j];
            s += c.x + c.y + c.z + c.w;
        }
    }
    sh[tid] = s;
    __syncthreads();
    for (int off = 1; off < 1024; off <<= 1) {
        int add = (tid >= off) ? sh[tid - off] : 0;
        __syncthreads();
        sh[tid] += add;
        __syncthreads();
    }
    int run = (tid == 0) ? 0 : sh[tid - 1];
    if (beg < NN) {
#pragma unroll
        for (int j = 0; j < 25; j++) {
            int4 c = *(const int4*)&g_cnt[beg + 4 * j];
            int4 rp;
            rp.x = run;            run += c.x;
            rp.y = run;            run += c.y;
            rp.z = run;            run += c.z;
            rp.w = run;            run += c.w;
            *(int4*)&g_rowptr[beg + 4 * j] = rp;
            float4 d;
            d.x = rsqrtf(1.0f + (float)c.x);
            d.y = rsqrtf(1.0f + (float)c.y);
            d.z = rsqrtf(1.0f + (float)c.z);
            d.w = rsqrtf(1.0f + (float)c.w);
            *(float4*)&g_dinv[beg + 4 * j] = d;
        }
    }
}

// ---------------- GEMM (tensor core, bf16x3, f32 A split in-kernel) --------
// g_bufA = A @ W, D = Ahi*Whi + Ahi*Wlo + Alo*Whi (fp32 accum).
// Block: 256 thr = 8 warps (4m x 2n), tile 128m x 64n, warp 32m x 32n.
// FILL: after tile store, block writes its 1024-edge slice of epack
// (atomic-free: slot idx precomputed in stage1). L2-bound tail overlaps
// other blocks' L1/tensor-bound mainloop.
#define A_STR 136
#define W_STR 72
#define MSMEM ((2 * 128 * A_STR + 2 * 128 * W_STR) * 2)
#define EPB 1024      // 1564 blocks * 1024 >= NEDGE

template <int NTOT, bool FILL>
__global__ void __launch_bounds__(256) k_mma(const float* __restrict__ Aext, int wsel) {
    extern __shared__ char sm[];
    __nv_bfloat16* sa_hi = (__nv_bfloat16*)sm;            // [128][A_STR]
    __nv_bfloat16* sa_lo = sa_hi + 128 * A_STR;
    __nv_bfloat16* sw_hi = sa_lo + 128 * A_STR;           // [128][W_STR]
    __nv_bfloat16* sw_lo = sw_hi + 128 * W_STR;
    const __nv_bfloat16* Whi = wsel_hi(wsel);
    const __nv_bfloat16* Wlo = wsel_lo(wsel);
    const float* A = Aext ? Aext : g_bufB;

    float* C = g_bufA;
    const int tid = threadIdx.x;
    const int row0 = blockIdx.x * 128;
    const int ct = blockIdx.y;

#pragma unroll
    for (int i = tid; i < 128 * 16; i += 256) {
        int r = i >> 4, q = i & 15;
        int gr = min(row0 + r, NN - 1);
        float4 v0 = *(const float4*)(A + (size_t)gr * 128 + 8 * q);
        float4 v1 = *(const float4*)(A + (size_t)gr * 128 + 8 * q + 4);
        uint4 ph, pl;
        split4(v0, &ph.x, &pl.x);
        split4(v1, &ph.z, &pl.z);
        *(uint4*)(sa_hi + r * A_STR + 8 * q) = ph;
        *(uint4*)(sa_lo + r * A_STR + 8 * q) = pl;
    }
#pragma unroll
    for (int i = tid; i < 128 * 8; i += 256) {
        int k = i >> 3, q = i & 7;
        *(uint4*)(sw_hi + k * W_STR + 8 * q) = *(const uint4*)(Whi + (size_t)k * NTOT + ct * 64 + 8 * q);
        *(uint4*)(sw_lo + k * W_STR + 8 * q) = *(const uint4*)(Wlo + (size_t)k * NTOT + ct * 64 + 8 * q);
    }
    __syncthreads();

    const int warp = tid >> 5, lane = tid & 31;
    const int wm = warp >> 1, wn = warp & 1;
    const int m0 = wm * 32, n0 = wn * 32;
    const int arow = lane & 15;
    const int acol = (lane >> 4) << 3;
    const int bkoff = lane & 15;
    const int bnoff = (lane >> 4) << 3;

    float acc[2][4][4];
#pragma unroll
    for (int fm = 0; fm < 2; fm++)
#pragma unroll
        for (int fn = 0; fn < 4; fn++)
#pragma unroll
            for (int j = 0; j < 4; j++) acc[fm][fn][j] = 0.0f;

#pragma unroll
    for (int s = 0; s < 8; s++) {
        const int k0 = s * 16;
        uint32_t ah[2][4], al[2][4], bh[4][2], bl[4][2];
#pragma unroll
        for (int fm = 0; fm < 2; fm++) {
            int r = m0 + fm * 16 + arow;
            ldsm_x4(s2u(sa_hi + r * A_STR + k0 + acol), ah[fm][0], ah[fm][1], ah[fm][2], ah[fm][3]);
            ldsm_x4(s2u(sa_lo + r * A_STR + k0 + acol), al[fm][0], al[fm][1], al[fm][2], al[fm][3]);
        }
#pragma unroll
        for (int f2 = 0; f2 < 2; f2++) {
            int nc = n0 + f2 * 16 + bnoff;
            ldsm_x4t(s2u(sw_hi + (k0 + bkoff) * W_STR + nc),
                     bh[2 * f2][0], bh[2 * f2][1], bh[2 * f2 + 1][0], bh[2 * f2 + 1][1]);
            ldsm_x4t(s2u(sw_lo + (k0 + bkoff) * W_STR + nc),
                     bl[2 * f2][0], bl[2 * f2][1], bl[2 * f2 + 1][0], bl[2 * f2 + 1][1]);
        }
#pragma unroll
        for (int fm = 0; fm < 2; fm++)
#pragma unroll
            for (int fn = 0; fn < 4; fn++) {
                mma_bf16(acc[fm][fn], ah[fm], bh[fn]);
                mma_bf16(acc[fm][fn], ah[fm], bl[fn]);
                mma_bf16(acc[fm][fn], al[fm], bh[fn]);
            }
    }

#pragma unroll
    for (int fm = 0; fm < 2; fm++) {
        int r = row0 + m0 + fm * 16 + (lane >> 2);
#pragma unroll
        for (int fn = 0; fn < 4; fn++) {
            int c = ct * 64 + n0 + fn * 8 + (lane & 3) * 2;
            if (r < NN)
                *(float2*)&C[(size_t)r * NTOT + c] = make_float2(acc[fm][fn][0], acc[fm][fn][1]);
            if (r + 8 < NN)
                *(float2*)&C[(size_t)(r + 8) * NTOT + c] = make_float2(acc[fm][fn][2], acc[fm][fn][3]);
        }
    }

    if (FILL) {
        // atomic-free CSR fill tail (slot idx packed in g_rows by stage1)
        int bid = blockIdx.y * gridDim.x + blockIdx.x;
        int e0 = bid * EPB;
#pragma unroll
        for (int i = tid; i < EPB; i += 256) {
            int e = e0 + i;
            if (e < NEDGE) {
                int packed = g_rows[e];
                int r = packed & 0x1FFFF;
                int idx = packed >> 17;            // non-negative (idx < 2^15)
                int c = g_cols[e];
                int pos = g_rowptr[r] + idx;
                float w = g_dinv[r] * g_dinv[c];
                g_epack[pos] = ((unsigned long long)__float_as_uint(w) << 32) |
                               (unsigned long long)(unsigned int)c;
            }
        }
    }
}

// ---------------- SPMM gather (CSR, packed edges), fused bias(+relu) -------
// Reads g_bufA (f32), writes f32 to Oext (or g_bufB if null). Unroll 8.
template <int K, bool RELU>
__global__ void k_spmm_gather(const float* __restrict__ bias,
                              float* __restrict__ Oext) {
    constexpr int L = K / 4;
    constexpr int RPW = 32 / L;
    const int warp = threadIdx.x >> 5;
    const int lane = threadIdx.x & 31;
    const int sub = lane / L;
    const int ll = lane % L;
    const int row = (blockIdx.x * 8 + warp) * RPW + sub;
    if (row >= NN) return;

    const float4* H4 = (const float4*)g_bufA;
    float* out = Oext ? Oext : g_bufB;

    const float dr = g_dinv[row];
    const int beg = g_rowptr[row];
    const int n = g_cnt[row];

    float4 h = H4[(size_t)row * L + ll];
    float wss = dr * dr;
    float4 acc = make_float4(wss * h.x, wss * h.y, wss * h.z, wss * h.w);

    int k = 0;
    const int n8 = n & ~7;
    for (; k < n8; k += 8) {
        unsigned long long p[8];
#pragma unroll
        for (int j = 0; j < 8; j++) p[j] = __ldg(&g_epack[beg + k + j]);
#pragma unroll
        for (int j = 0; j < 8; j++) {
            int c = (int)(unsigned int)p[j];
            float w = __uint_as_float((unsigned int)(p[j] >> 32));
            float4 v = H4[(size_t)c * L + ll];
            acc.x += w * v.x; acc.y += w * v.y; acc.z += w * v.z; acc.w += w * v.w;
        }
    }
    for (; k < n; k++) {
        unsigned long long p = __ldg(&g_epack[beg + k]);
        int c = (int)(unsigned int)p;
        float w = __uint_as_float((unsigned int)(p >> 32));
        float4 v = H4[(size_t)c * L + ll];
        acc.x += w * v.x; acc.y += w * v.y; acc.z += w * v.z; acc.w += w * v.w;
    }

    float4 b = ((const float4*)bias)[ll];
    acc.x += b.x; acc.y += b.y; acc.z += b.z; acc.w += b.w;
    if (RELU) {
        acc.x = fmaxf(acc.x, 0.0f); acc.y = fmaxf(acc.y, 0.0f);
        acc.z = fmaxf(acc.z, 0.0f); acc.w = fmaxf(acc.w, 0.0f);
    }
    ((float4*)out)[(size_t)row * L + ll] = acc;
}

// ---------------- launch ----------------
extern "C" void kernel_launch(void* const* d_in, const int* in_sizes, int n_in,
                              void* d_out, int out_size) {
    const float* x = (const float*)d_in[0];
    const int* ei = (const int*)d_in[1];
    const float* W0 = (const float*)d_in[2];
    const float* b0 = (const float*)d_in[3];
    const float* W1 = (const float*)d_in[4];
    const float* b1 = (const float*)d_in[5];
    const float* W2 = (const float*)d_in[6];
    const float* b2 = (const float*)d_in[7];
    float* out = (float*)d_out;

    const int gN = (NN + 255) / 256;              // 391
    const int gSpmm128 = (NN + 7) / 8;            // 12500
    const int gSpmm64 = (NN + 15) / 16;           // 6250
    const int gRowTiles = (NN + 127) / 128;       // 782

    cudaFuncSetAttribute(k_mma<128, true>, cudaFuncAttributeMaxDynamicSharedMemorySize, MSMEM);
    cudaFuncSetAttribute(k_mma<128, false>, cudaFuncAttributeMaxDynamicSharedMemorySize, MSMEM);
    cudaFuncSetAttribute(k_mma<64, false>, cudaFuncAttributeMaxDynamicSharedMemorySize, MSMEM);

    // 0: zero counts + dtype detect
    k_init<<<gN, 256>>>(ei);
    // 1: extract+count(+slot idx) | splitW0/1/2
    k_stage1<<<NB_STAGE1, 256>>>(ei, W0, W1, W2);
    // 2: scan + dinv
    k_scan_dinv<<<1, 1024>>>();
    // 3: layer-1 GEMM + atomic-free fill tail (profiled slot)
    k_mma<128, true><<<dim3(gRowTiles, 2), 256, MSMEM>>>(x, 0);
    // 4: layer-1 aggregate -> g_bufB
    k_spmm_gather<128, true><<<gSpmm128, 256>>>(b0, nullptr);
    // 5-6: layer 2
    k_mma<128, false><<<dim3(gRowTiles, 2), 256, MSMEM>>>(nullptr, 1);
    k_spmm_gather<128, true><<<gSpmm128, 256>>>(b1, nullptr);
    // 7-8: layer 3
    k_mma<64, false><<<dim3(gRowTiles, 1), 256, MSMEM>>>(nullptr, 2);
    k_spmm_gather<64, false><<<gSpmm64, 256>>>(b2, out);
}

// round 15
// speedup vs baseline: 1.0477x; 1.0477x over previous
#include <cuda_runtime.h>
#include <cuda_bf16.h>
#include <cstdint>

#define NN 100000
#define NEDGE 1600000

// ---------------- device scratch (no allocation; referenced by name only) --
__device__ int   g_is64;
__device__ int   g_rows[NEDGE];     // packed: row | (slot_idx << 17)
__device__ int   g_cols[NEDGE];
__device__ unsigned long long g_epack[NEDGE];   // {w:f32 << 32 | col:u32}
__device__ float g_dinv[NN];
__device__ int   g_cnt[NN];
__device__ int   g_rowptr[NN];
__device__ __align__(16) float g_bufA[(size_t)NN * 128];   // GEMM out (f32)
__device__ __align__(16) float g_bufB[(size_t)NN * 128];   // SPMM out (f32)
__device__ __align__(16) __nv_bfloat16 g_W0hi[128 * 128], g_W0lo[128 * 128];
__device__ __align__(16) __nv_bfloat16 g_W1hi[128 * 128], g_W1lo[128 * 128];
__device__ __align__(16) __nv_bfloat16 g_W2hi[128 * 64],  g_W2lo[128 * 64];

__device__ __forceinline__ const __nv_bfloat16* wsel_hi(int w) {
    return w == 0 ? g_W0hi : (w == 1 ? g_W1hi : g_W2hi);
}
__device__ __forceinline__ const __nv_bfloat16* wsel_lo(int w) {
    return w == 0 ? g_W0lo : (w == 1 ? g_W1lo : g_W2lo);
}

// ---------------- helpers ----------------
__device__ __forceinline__ uint32_t s2u(const void* p) {
    return (uint32_t)__cvta_generic_to_shared(p);
}
__device__ __forceinline__ void ldsm_x4(uint32_t addr, uint32_t& r0, uint32_t& r1,
                                        uint32_t& r2, uint32_t& r3) {
    asm volatile("ldmatrix.sync.aligned.m8n8.x4.shared.b16 {%0,%1,%2,%3}, [%4];"
                 : "=r"(r0), "=r"(r1), "=r"(r2), "=r"(r3) : "r"(addr));
}
__device__ __forceinline__ void ldsm_x4t(uint32_t addr, uint32_t& r0, uint32_t& r1,
                                         uint32_t& r2, uint32_t& r3) {
    asm volatile("ldmatrix.sync.aligned.m8n8.x4.trans.shared.b16 {%0,%1,%2,%3}, [%4];"
                 : "=r"(r0), "=r"(r1), "=r"(r2), "=r"(r3) : "r"(addr));
}
__device__ __forceinline__ void mma_bf16(float* c, const uint32_t* a, const uint32_t* b) {
    asm volatile(
        "mma.sync.aligned.m16n8k16.row.col.f32.bf16.bf16.f32 "
        "{%0,%1,%2,%3},{%4,%5,%6,%7},{%8,%9},{%0,%1,%2,%3};"
        : "+f"(c[0]), "+f"(c[1]), "+f"(c[2]), "+f"(c[3])
        : "r"(a[0]), "r"(a[1]), "r"(a[2]), "r"(a[3]), "r"(b[0]), "r"(b[1]));
}
__device__ __forceinline__ void split_bf16(float v, unsigned short& hi, unsigned short& lo) {
    __nv_bfloat16 h = __float2bfloat16(v);
    float r = v - __bfloat162float(h);
    __nv_bfloat16 l = __float2bfloat16(r);
    hi = *(unsigned short*)&h;
    lo = *(unsigned short*)&l;
}
__device__ __forceinline__ void split4(float4 v, uint32_t* ph, uint32_t* pl) {
    unsigned short h[4], l[4];
    split_bf16(v.x, h[0], l[0]);
    split_bf16(v.y, h[1], l[1]);
    split_bf16(v.z, h[2], l[2]);
    split_bf16(v.w, h[3], l[3]);
    ph[0] = (uint32_t)h[0] | ((uint32_t)h[1] << 16);
    ph[1] = (uint32_t)h[2] | ((uint32_t)h[3] << 16);
    pl[0] = (uint32_t)l[0] | ((uint32_t)l[1] << 16);
    pl[1] = (uint32_t)l[2] | ((uint32_t)l[3] << 16);
}
// L2-only (cg) float4 load — random gather rows never hit L1.
__device__ __forceinline__ float4 ldcg4(const float4* p) {
    float4 v;
    asm volatile("ld.global.cg.v4.f32 {%0,%1,%2,%3}, [%4];"
                 : "=f"(v.x), "=f"(v.y), "=f"(v.z), "=f"(v.w) : "l"(p));
    return v;
}

// ---------------- k_init: zero cnt + dtype detect (block 0) ----------------
__global__ void k_init(const int* __restrict__ ei) {
    int i = blockIdx.x * blockDim.x + threadIdx.x;
    if (i < NN) g_cnt[i] = 0;
    if (blockIdx.x == 0) {
        __shared__ int bad;
        if (threadIdx.x == 0) bad = 0;
        __syncthreads();
        for (int k = threadIdx.x; k < 1024; k += blockDim.x) {
            int lo = ei[2 * k], hi = ei[2 * k + 1];
            if (hi != 0 || lo < 0 || lo >= NN) bad = 1;
        }
        __syncthreads();
        if (threadIdx.x == 0) g_is64 = (bad == 0) ? 1 : 0;
    }
}

// ---------------- k_stage1: extract+count(+slot idx) | splitW0/1/2 ---------
#define NB_EXTRACT 6250
#define NB_W0 64
#define NB_W1 64
#define NB_W2 32
#define NB_STAGE1 (NB_EXTRACT + NB_W0 + NB_W1 + NB_W2)

__device__ __forceinline__ void do_splitW(const float* __restrict__ W, int i, int n,
                                          __nv_bfloat16* hi, __nv_bfloat16* lo) {
    if (i >= n) return;
    unsigned short h, l;
    split_bf16(W[i], h, l);
    hi[i] = *(__nv_bfloat16*)&h;
    lo[i] = *(__nv_bfloat16*)&l;
}

__global__ void k_stage1(const int* __restrict__ ei,
                         const float* __restrict__ W0, const float* __restrict__ W1,
                         const float* __restrict__ W2) {
    const int b = blockIdx.x;
    const int tid = threadIdx.x;
    if (b < NB_EXTRACT) {
        int e = b * 256 + tid;
        if (e >= NEDGE) return;
        int r, c;
        if (g_is64) {
            r = ei[2 * e];
            c = ei[2 * (NEDGE + e)];
        } else {
            r = ei[e];
            c = ei[NEDGE + e];
        }
        r = min(max(r, 0), NN - 1);
        c = min(max(c, 0), NN - 1);
        int idx = atomicAdd(&g_cnt[r], 1) & 0x7FFF;   // slot within row
        g_rows[e] = r | (idx << 17);                  // NN < 2^17
        g_cols[e] = c;
    } else if (b < NB_EXTRACT + NB_W0) {
        do_splitW(W0, (b - NB_EXTRACT) * 256 + tid, 128 * 128, g_W0hi, g_W0lo);
    } else if (b < NB_EXTRACT + NB_W0 + NB_W1) {
        do_splitW(W1, (b - NB_EXTRACT - NB_W0) * 256 + tid, 128 * 128, g_W1hi, g_W1lo);
    } else {
        do_splitW(W2, (b - NB_EXTRACT - NB_W0 - NB_W1) * 256 + tid, 128 * 64, g_W2hi, g_W2lo);
    }
}

// ---------------- k_scan_dinv: single-block scan of g_cnt + dinv -----------
__global__ void k_scan_dinv() {
    __shared__ int sh[1024];
    const int tid = threadIdx.x;
    const int beg = tid * 100;
    int s = 0;
    if (beg < NN) {
#pragma unroll
        for (int j = 0; j < 25; j++) {
            int4 c = *(const int4*)&g_cnt[beg + 4 * j];
            s += c.x + c.y + c.z + c.w;
        }
    }
    sh[tid] = s;
    __syncthreads();
    for (int off = 1; off < 1024; off <<= 1) {
        int add = (tid >= off) ? sh[tid - off] : 0;
        __syncthreads();
        sh[tid] += add;
        __syncthreads();
    }
    int run = (tid == 0) ? 0 : sh[tid - 1];
    if (beg < NN) {
#pragma unroll
        for (int j = 0; j < 25; j++) {
            int4 c = *(const int4*)&g_cnt[beg + 4 * j];
            int4 rp;
            rp.x = run;            run += c.x;
            rp.y = run;            run += c.y;
            rp.z = run;            run += c.z;
            rp.w = run;            run += c.w;
            *(int4*)&g_rowptr[beg + 4 * j] = rp;
            float4 d;
            d.x = rsqrtf(1.0f + (float)c.x);
            d.y = rsqrtf(1.0f + (float)c.y);
            d.z = rsqrtf(1.0f + (float)c.z);
            d.w = rsqrtf(1.0f + (float)c.w);
            *(float4*)&g_dinv[beg + 4 * j] = d;
        }
    }
}

// ---------------- k_fill: atomic-free CSR fill (slot idx from stage1) ------
__global__ void k_fill() {
    int e = blockIdx.x * blockDim.x + threadIdx.x;
    if (e >= NEDGE) return;
    int packed = g_rows[e];
    int r = packed & 0x1FFFF;
    int idx = packed >> 17;            // non-negative (idx < 2^15)
    int c = g_cols[e];
    int pos = g_rowptr[r] + idx;
    float w = g_dinv[r] * g_dinv[c];
    g_epack[pos] = ((unsigned long long)__float_as_uint(w) << 32) |
                   (unsigned long long)(unsigned int)c;
}

// ---------------- GEMM (tensor core, bf16x3, f32 A split in-kernel) --------
// g_bufA = A @ W, D = Ahi*Whi + Ahi*Wlo + Alo*Whi (fp32 accum).
// Block: 256 thr = 8 warps (4m x 2n), tile 128m x 64n, warp 32m x 32n.
#define A_STR 136
#define W_STR 72
#define MSMEM ((2 * 128 * A_STR + 2 * 128 * W_STR) * 2)

template <int NTOT>
__global__ void __launch_bounds__(256) k_mma(const float* __restrict__ Aext, int wsel) {
    extern __shared__ char sm[];
    __nv_bfloat16* sa_hi = (__nv_bfloat16*)sm;            // [128][A_STR]
    __nv_bfloat16* sa_lo = sa_hi + 128 * A_STR;
    __nv_bfloat16* sw_hi = sa_lo + 128 * A_STR;           // [128][W_STR]
    __nv_bfloat16* sw_lo = sw_hi + 128 * W_STR;
    const __nv_bfloat16* Whi = wsel_hi(wsel);
    const __nv_bfloat16* Wlo = wsel_lo(wsel);
    const float* A = Aext ? Aext : g_bufB;

    float* C = g_bufA;
    const int tid = threadIdx.x;
    const int row0 = blockIdx.x * 128;
    const int ct = blockIdx.y;

#pragma unroll
    for (int i = tid; i < 128 * 16; i += 256) {
        int r = i >> 4, q = i & 15;
        int gr = min(row0 + r, NN - 1);
        float4 v0 = *(const float4*)(A + (size_t)gr * 128 + 8 * q);
        float4 v1 = *(const float4*)(A + (size_t)gr * 128 + 8 * q + 4);
        uint4 ph, pl;
        split4(v0, &ph.x, &pl.x);
        split4(v1, &ph.z, &pl.z);
        *(uint4*)(sa_hi + r * A_STR + 8 * q) = ph;
        *(uint4*)(sa_lo + r * A_STR + 8 * q) = pl;
    }
#pragma unroll
    for (int i = tid; i < 128 * 8; i += 256) {
        int k = i >> 3, q = i & 7;
        *(uint4*)(sw_hi + k * W_STR + 8 * q) = *(const uint4*)(Whi + (size_t)k * NTOT + ct * 64 + 8 * q);
        *(uint4*)(sw_lo + k * W_STR + 8 * q) = *(const uint4*)(Wlo + (size_t)k * NTOT + ct * 64 + 8 * q);
    }
    __syncthreads();

    const int warp = tid >> 5, lane = tid & 31;
    const int wm = warp >> 1, wn = warp & 1;
    const int m0 = wm * 32, n0 = wn * 32;
    const int arow = lane & 15;
    const int acol = (lane >> 4) << 3;
    const int bkoff = lane & 15;
    const int bnoff = (lane >> 4) << 3;

    float acc[2][4][4];
#pragma unroll
    for (int fm = 0; fm < 2; fm++)
#pragma unroll
        for (int fn = 0; fn < 4; fn++)
#pragma unroll
            for (int j = 0; j < 4; j++) acc[fm][fn][j] = 0.0f;

#pragma unroll
    for (int s = 0; s < 8; s++) {
        const int k0 = s * 16;
        uint32_t ah[2][4], al[2][4], bh[4][2], bl[4][2];
#pragma unroll
        for (int fm = 0; fm < 2; fm++) {
            int r = m0 + fm * 16 + arow;
            ldsm_x4(s2u(sa_hi + r * A_STR + k0 + acol), ah[fm][0], ah[fm][1], ah[fm][2], ah[fm][3]);
            ldsm_x4(s2u(sa_lo + r * A_STR + k0 + acol), al[fm][0], al[fm][1], al[fm][2], al[fm][3]);
        }
#pragma unroll
        for (int f2 = 0; f2 < 2; f2++) {
            int nc = n0 + f2 * 16 + bnoff;
            ldsm_x4t(s2u(sw_hi + (k0 + bkoff) * W_STR + nc),
                     bh[2 * f2][0], bh[2 * f2][1], bh[2 * f2 + 1][0], bh[2 * f2 + 1][1]);
            ldsm_x4t(s2u(sw_lo + (k0 + bkoff) * W_STR + nc),
                     bl[2 * f2][0], bl[2 * f2][1], bl[2 * f2 + 1][0], bl[2 * f2 + 1][1]);
        }
#pragma unroll
        for (int fm = 0; fm < 2; fm++)
#pragma unroll
            for (int fn = 0; fn < 4; fn++) {
                mma_bf16(acc[fm][fn], ah[fm], bh[fn]);
                mma_bf16(acc[fm][fn], ah[fm], bl[fn]);
                mma_bf16(acc[fm][fn], al[fm], bh[fn]);
            }
    }

#pragma unroll
    for (int fm = 0; fm < 2; fm++) {
        int r = row0 + m0 + fm * 16 + (lane >> 2);
#pragma unroll
        for (int fn = 0; fn < 4; fn++) {
            int c = ct * 64 + n0 + fn * 8 + (lane & 3) * 2;
            if (r < NN)
                *(float2*)&C[(size_t)r * NTOT + c] = make_float2(acc[fm][fn][0], acc[fm][fn][1]);
            if (r + 8 < NN)
                *(float2*)&C[(size_t)(r + 8) * NTOT + c] = make_float2(acc[fm][fn][2], acc[fm][fn][3]);
        }
    }
}

// ---------------- SPMM gather (CSR, packed edges), fused bias(+relu) -------
// Reads g_bufA (f32, L2-only loads), writes f32 to Oext (or g_bufB if null).
template <int K, bool RELU>
__global__ void k_spmm_gather(const float* __restrict__ bias,
                              float* __restrict__ Oext) {
    constexpr int L = K / 4;
    constexpr int RPW = 32 / L;
    const int warp = threadIdx.x >> 5;
    const int lane = threadIdx.x & 31;
    const int sub = lane / L;
    const int ll = lane % L;
    const int row = (blockIdx.x * 8 + warp) * RPW + sub;
    if (row >= NN) return;

    const float4* H4 = (const float4*)g_bufA;
    float* out = Oext ? Oext : g_bufB;

    const float dr = g_dinv[row];
    const int beg = g_rowptr[row];
    const int n = g_cnt[row];

    float4 h = H4[(size_t)row * L + ll];
    float wss = dr * dr;
    float4 acc = make_float4(wss * h.x, wss * h.y, wss * h.z, wss * h.w);

    int k = 0;
    const int n8 = n & ~7;
    for (; k < n8; k += 8) {
        unsigned long long p[8];
#pragma unroll
        for (int j = 0; j < 8; j++) p[j] = __ldg(&g_epack[beg + k + j]);
#pragma unroll
        for (int j = 0; j < 8; j++) {
            int c = (int)(unsigned int)p[j];
            float w = __uint_as_float((unsigned int)(p[j] >> 32));
            float4 v = ldcg4(&H4[(size_t)c * L + ll]);
            acc.x += w * v.x; acc.y += w * v.y; acc.z += w * v.z; acc.w += w * v.w;
        }
    }
    for (; k < n; k++) {
        unsigned long long p = __ldg(&g_epack[beg + k]);
        int c = (int)(unsigned int)p;
        float w = __uint_as_float((unsigned int)(p >> 32));
        float4 v = ldcg4(&H4[(size_t)c * L + ll]);
        acc.x += w * v.x; acc.y += w * v.y; acc.z += w * v.z; acc.w += w * v.w;
    }

    float4 b = ((const float4*)bias)[ll];
    acc.x += b.x; acc.y += b.y; acc.z += b.z; acc.w += b.w;
    if (RELU) {
        acc.x = fmaxf(acc.x, 0.0f); acc.y = fmaxf(acc.y, 0.0f);
        acc.z = fmaxf(acc.z, 0.0f); acc.w = fmaxf(acc.w, 0.0f);
    }
    ((float4*)out)[(size_t)row * L + ll] = acc;
}

// ---------------- launch ----------------
extern "C" void kernel_launch(void* const* d_in, const int* in_sizes, int n_in,
                              void* d_out, int out_size) {
    const float* x = (const float*)d_in[0];
    const int* ei = (const int*)d_in[1];
    const float* W0 = (const float*)d_in[2];
    const float* b0 = (const float*)d_in[3];
    const float* W1 = (const float*)d_in[4];
    const float* b1 = (const float*)d_in[5];
    const float* W2 = (const float*)d_in[6];
    const float* b2 = (const float*)d_in[7];
    float* out = (float*)d_out;

    const int gN = (NN + 255) / 256;              // 391
    const int gE = (NEDGE + 255) / 256;           // 6250
    const int gSpmm128 = (NN + 7) / 8;            // 12500
    const int gSpmm64 = (NN + 15) / 16;           // 6250
    const int gRowTiles = (NN + 127) / 128;       // 782

    cudaFuncSetAttribute(k_mma<128>, cudaFuncAttributeMaxDynamicSharedMemorySize, MSMEM);
    cudaFuncSetAttribute(k_mma<64>, cudaFuncAttributeMaxDynamicSharedMemorySize, MSMEM);

    // 0: zero counts + dtype detect
    k_init<<<gN, 256>>>(ei);
    // 1: extract+count(+slot idx) | splitW0/1/2
    k_stage1<<<NB_STAGE1, 256>>>(ei, W0, W1, W2);
    // 2: scan + dinv
    k_scan_dinv<<<1, 1024>>>();
    // 3: atomic-free CSR fill (profiled slot)
    k_fill<<<gE, 256>>>();
    // 4: layer-1 GEMM (x read directly as f32, split in-kernel)
    k_mma<128><<<dim3(gRowTiles, 2), 256, MSMEM>>>(x, 0);
    // 5: layer-1 aggregate -> g_bufB
    k_spmm_gather<128, true><<<gSpmm128, 256>>>(b0, nullptr);
    // 6-7: layer 2
    k_mma<128><<<dim3(gRowTiles, 2), 256, MSMEM>>>(nullptr, 1);
    k_spmm_gather<128, true><<<gSpmm128, 256>>>(b1, nullptr);
    // 8-9: layer 3
    k_mma<64><<<dim3(gRowTiles, 1), 256, MSMEM>>>(nullptr, 2);
    k_spmm_gather<64, false><<<gSpmm64, 256>>>(b2, out);
}